// round 13
// baseline (speedup 1.0000x reference)
#include <cuda_runtime.h>
#include <cuda_fp16.h>
#include <math.h>
#include <stdint.h>

// out = ((cos-product head)(x @ Wp^T + bp + theta)) @ Wc^T + bc
// Quantum head closed form (CNOT ring = linear XOR map on basis bits):
//   expz[w] = prod_{j=0..w} cos(ang_j)  (w>=1);  expz[0] = prod_{j=1..7} cos(ang_j)
//
// Tensor path: mma.sync m16n8k16 fp16 (HMMA; tcgen05 PTX rejected at sm_103 target).
// GEMM1 reads fp32 x directly (cp.async fp32 stage + in-smem fp16 convert),
// eliminating the x pre-conversion pass. Weights pre-converted (small).
// Error ledger (measured R6-R11): combined fp16 truncation 5.7e-4 < 1e-3 gate.

#define M_DIM 4096
#define N_DIM 768
#define KD    768
#define BM    128
#define BN    192
#define BK    64
#define NITER (KD / BK)        // 12
#define THREADS 256

#define AROWS   BM
#define CPAD    (BN + 4)

// ---- GEMM1 smem: 3 stages x (A32 32K @0 | A16 16K @32768 | B16 24K @49152) ----
#define S1_A16   32768
#define S1_B16   49152
#define S1_STAGE 73728                 // 49152 + 192*128
#define S1_SMEM  (3 * S1_STAGE)        // 221184 (< 227KB opt-in)

// ---- GEMM2 smem: 4 stages x (A16+B16 interleaved rows, 320*128) ----
#define S2_STAGE ((BM + BN) * 128)     // 40960
#define S2_SMEM  (4 * S2_STAGE)        // 163840

// ---- device scratch (allocation-free rule) ----
__device__ __half g_Bp[(size_t)N_DIM * KD];
__device__ __half g_Bc[(size_t)N_DIM * KD];
__device__ __half g_E[(size_t)M_DIM * KD];

// ---- helpers ----
__device__ __forceinline__ uint32_t smem_u32(const void* p) {
    uint32_t a;
    asm("{ .reg .u64 t; cvta.to.shared.u64 t, %1; cvt.u32.u64 %0, t; }" : "=r"(a) : "l"(p));
    return a;
}
__device__ __forceinline__ void cp_async16(uint32_t dst, const void* src) {
    asm volatile("cp.async.cg.shared.global [%0], [%1], 16;" :: "r"(dst), "l"(src));
}
__device__ __forceinline__ void ldsm4(uint32_t* r, uint32_t addr) {
    asm volatile("ldmatrix.sync.aligned.m8n8.x4.shared.b16 {%0,%1,%2,%3}, [%4];"
                 : "=r"(r[0]), "=r"(r[1]), "=r"(r[2]), "=r"(r[3]) : "r"(addr));
}
__device__ __forceinline__ void mma_f16(float* c, const uint32_t* a, uint32_t b0, uint32_t b1) {
    asm volatile(
        "mma.sync.aligned.m16n8k16.row.col.f32.f16.f16.f32 "
        "{%0,%1,%2,%3}, {%4,%5,%6,%7}, {%8,%9}, {%0,%1,%2,%3};"
        : "+f"(c[0]), "+f"(c[1]), "+f"(c[2]), "+f"(c[3])
        : "r"(a[0]), "r"(a[1]), "r"(a[2]), "r"(a[3]), "r"(b0), "r"(b1));
}

// ---- fp32 -> fp16 convert for weights only (wp, wc) ----
__global__ void conv_kernel(const float* __restrict__ wp,
                            const float* __restrict__ wc) {
    const int n16w = N_DIM * KD / 16;   // 36864
    int i = blockIdx.x * blockDim.x + threadIdx.x;
    const float* src; __half* dst; int j;
    if (i < n16w)          { src = wp; dst = g_Bp; j = i; }
    else if (i < 2 * n16w) { src = wc; dst = g_Bc; j = i - n16w; }
    else return;
    float4 v0 = ((const float4*)src)[j * 4 + 0];
    float4 v1 = ((const float4*)src)[j * 4 + 1];
    float4 v2 = ((const float4*)src)[j * 4 + 2];
    float4 v3 = ((const float4*)src)[j * 4 + 3];
    __half2 h0 = __floats2half2_rn(v0.x, v0.y);
    __half2 h1 = __floats2half2_rn(v0.z, v0.w);
    __half2 h2 = __floats2half2_rn(v1.x, v1.y);
    __half2 h3 = __floats2half2_rn(v1.z, v1.w);
    __half2 h4 = __floats2half2_rn(v2.x, v2.y);
    __half2 h5 = __floats2half2_rn(v2.z, v2.w);
    __half2 h6 = __floats2half2_rn(v3.x, v3.y);
    __half2 h7 = __floats2half2_rn(v3.z, v3.w);
    ((uint4*)dst)[j * 2 + 0] = make_uint4(*(uint32_t*)&h0, *(uint32_t*)&h1,
                                          *(uint32_t*)&h2, *(uint32_t*)&h3);
    ((uint4*)dst)[j * 2 + 1] = make_uint4(*(uint32_t*)&h4, *(uint32_t*)&h5,
                                          *(uint32_t*)&h6, *(uint32_t*)&h7);
}

// ---- GEMM1: angles = x(fp32) @ Wp^T; quantum head epilogue -> E (fp16) ----
// 128x192 tile, 8 warps 2x4 (64x48), BK=64, 3-stage cp.async (A fp32 + B fp16),
// per-stage in-smem fp32->fp16 convert of A, XOR-swizzled fp16 rows.
__global__ __launch_bounds__(THREADS)
void qgemm1(const float* __restrict__ X,
            const __half* __restrict__ B,
            const float* __restrict__ bias,
            const float* __restrict__ theta,
            __half* __restrict__ E)
{
    extern __shared__ char smem[];
    const uint32_t sb = smem_u32(smem);
    const int tid = threadIdx.x;
    const int l = tid & 31;
    const int wid = tid >> 5;
    const int warp_m = wid & 1;
    const int warp_n = wid >> 1;
    const int bm = blockIdx.y * BM;
    const int bn = blockIdx.x * BN;

    float acc[4][6][4];
#pragma unroll
    for (int mi = 0; mi < 4; mi++)
#pragma unroll
        for (int ni = 0; ni < 6; ni++)
#pragma unroll
            for (int q = 0; q < 4; q++) acc[mi][ni][q] = 0.0f;

    // per stage: A32 = 128 rows x 64 fp32 (2048 16B chunks, linear 256B rows)
    //            B16 = 192 rows x 64 fp16 (1536 chunks, swizzled 128B rows)
    auto load_stage = [&](int s, int k0) {
        uint32_t stage = sb + s * S1_STAGE;
#pragma unroll
        for (int i = 0; i < 14; i++) {
            int id = tid + i * THREADS;
            if (id < 2048) {
                int r = id >> 4, cc = id & 15;
                cp_async16(stage + r * 256 + cc * 16,
                           X + (size_t)(bm + r) * KD + k0 + cc * 4);
            } else {
                int id2 = id - 2048;
                int row = id2 >> 3, c = id2 & 7;
                cp_async16(stage + S1_B16 + row * 128 + (c ^ (row & 7)) * 16,
                           B + (size_t)(bn + row) * KD + k0 + c * 8);
            }
        }
    };

    load_stage(0, 0);
    asm volatile("cp.async.commit_group;");
    load_stage(1, BK);
    asm volatile("cp.async.commit_group;");

    const int lr = l & 15;
    const int lc = l >> 4;
    const int lx = l & 7;

    for (int kt = 0; kt < NITER; kt++) {
        asm volatile("cp.async.wait_group 1;");
        __syncthreads();

        const uint32_t stage = sb + (kt % 3) * S1_STAGE;
        // convert A32 -> A16 (swizzled fp16 layout identical to weights path)
#pragma unroll
        for (int i = 0; i < 4; i++) {
            int id = tid + i * THREADS;     // 0..1023 chunk ids
            int row = id >> 3, c = id & 7;
            const float* p = (const float*)(smem + (kt % 3) * S1_STAGE) + row * 64 + c * 8;
            float4 f0 = *(const float4*)p;
            float4 f1 = *(const float4*)(p + 4);
            __half2 h0 = __floats2half2_rn(f0.x, f0.y);
            __half2 h1 = __floats2half2_rn(f0.z, f0.w);
            __half2 h2 = __floats2half2_rn(f1.x, f1.y);
            __half2 h3 = __floats2half2_rn(f1.z, f1.w);
            *(uint4*)(smem + (kt % 3) * S1_STAGE + S1_A16 + row * 128 + (c ^ (row & 7)) * 16) =
                make_uint4(*(uint32_t*)&h0, *(uint32_t*)&h1, *(uint32_t*)&h2, *(uint32_t*)&h3);
        }

        if (kt + 2 < NITER) load_stage((kt + 2) % 3, (kt + 2) * BK);
        asm volatile("cp.async.commit_group;");
        __syncthreads();   // converted A16 visible to all warps

        const uint32_t stgA = stage + S1_A16;
        const uint32_t stgB = stage + S1_B16;
#pragma unroll
        for (int ksub = 0; ksub < 4; ksub++) {
            const int cs = (2 * ksub + lc) ^ lx;
            uint32_t a[4][4], b[3][4];
#pragma unroll
            for (int mi = 0; mi < 4; mi++) {
                int row = warp_m * 64 + mi * 16 + lr;
                ldsm4(a[mi], stgA + row * 128 + cs * 16);
            }
#pragma unroll
            for (int q = 0; q < 3; q++) {
                int row = warp_n * 48 + q * 16 + lr;
                ldsm4(b[q], stgB + row * 128 + cs * 16);
            }
#pragma unroll
            for (int mi = 0; mi < 4; mi++)
#pragma unroll
                for (int q = 0; q < 3; q++) {
                    mma_f16(acc[mi][2 * q],     a[mi], b[q][0], b[q][2]);
                    mma_f16(acc[mi][2 * q + 1], a[mi], b[q][1], b[q][3]);
                }
        }
    }
    asm volatile("cp.async.wait_group 0;");
    __syncthreads();

    // epilogue: stage accums through smem, closed-form quantum head per 8-col group
    float* Cs = (float*)smem;
#pragma unroll
    for (int mi = 0; mi < 4; mi++)
#pragma unroll
        for (int ni = 0; ni < 6; ni++) {
            int row = warp_m * 64 + mi * 16 + (l >> 2);
            int col = warp_n * 48 + ni * 8 + (l & 3) * 2;
            *(float2*)&Cs[row * CPAD + col]       = make_float2(acc[mi][ni][0], acc[mi][ni][1]);
            *(float2*)&Cs[(row + 8) * CPAD + col] = make_float2(acc[mi][ni][2], acc[mi][ni][3]);
        }
    __syncthreads();

    float th[8];
#pragma unroll
    for (int j = 0; j < 8; j++) th[j] = theta[j];

#pragma unroll
    for (int i = 0; i < 12; i++) {
        int g = tid + i * THREADS;
        int r = g / 24;
        int h = g - r * 24;
        int nn = bn + h * 8;
        const float* src = &Cs[r * CPAD + h * 8];
        float cc[8];
#pragma unroll
        for (int j = 0; j < 8; j++)
            cc[j] = __cosf(src[j] + bias[nn + j] + th[j]);
        float o[8];
        float p = cc[0];
#pragma unroll
        for (int j = 1; j < 8; j++) { p *= cc[j]; o[j] = p; }
        float sp = cc[1];
#pragma unroll
        for (int j = 2; j < 8; j++) sp *= cc[j];
        o[0] = sp;
        uint32_t hv[4];
#pragma unroll
        for (int q = 0; q < 4; q++) {
            __half2 hh = __floats2half2_rn(o[2 * q], o[2 * q + 1]);
            hv[q] = *(uint32_t*)&hh;
        }
        *(uint4*)(E + (size_t)(bm + r) * KD + nn) = make_uint4(hv[0], hv[1], hv[2], hv[3]);
    }
}

// ---- GEMM2: out = E(fp16) @ Wc^T + bc (unchanged known-good 4-stage kernel) ----
__global__ __launch_bounds__(THREADS)
void gemm2(const __half* __restrict__ A,
           const __half* __restrict__ B,
           const float* __restrict__ bias,
           float* __restrict__ out)
{
    extern __shared__ char smem[];
    const uint32_t sb = smem_u32(smem);
    const int tid = threadIdx.x;
    const int l = tid & 31;
    const int wid = tid >> 5;
    const int warp_m = wid & 1;
    const int warp_n = wid >> 1;
    const int bm = blockIdx.y * BM;
    const int bn = blockIdx.x * BN;

    float acc[4][6][4];
#pragma unroll
    for (int mi = 0; mi < 4; mi++)
#pragma unroll
        for (int ni = 0; ni < 6; ni++)
#pragma unroll
            for (int q = 0; q < 4; q++) acc[mi][ni][q] = 0.0f;

    auto load_stage = [&](int s, int k0) {
        uint32_t stage = sb + s * S2_STAGE;
#pragma unroll
        for (int i = 0; i < 10; i++) {
            int id = tid + i * THREADS;
            int row = id >> 3;
            int c = id & 7;
            int cs = c ^ (row & 7);
            uint32_t dst = stage + row * 128 + cs * 16;
            const __half* g;
            if (row < AROWS) g = A + (size_t)(bm + row) * KD + k0 + c * 8;
            else             g = B + (size_t)(bn + row - AROWS) * KD + k0 + c * 8;
            cp_async16(dst, g);
        }
    };

    load_stage(0, 0);
    asm volatile("cp.async.commit_group;");
    load_stage(1, BK);
    asm volatile("cp.async.commit_group;");
    load_stage(2, 2 * BK);
    asm volatile("cp.async.commit_group;");

    const int lr = l & 15;
    const int lc = l >> 4;
    const int lx = l & 7;

    for (int kt = 0; kt < NITER; kt++) {
        asm volatile("cp.async.wait_group 2;");
        __syncthreads();

        if (kt + 3 < NITER) load_stage((kt + 3) & 3, (kt + 3) * BK);
        asm volatile("cp.async.commit_group;");

        const uint32_t stage = sb + (kt & 3) * S2_STAGE;
#pragma unroll
        for (int ksub = 0; ksub < 4; ksub++) {
            const int cs = (2 * ksub + lc) ^ lx;
            uint32_t a[4][4], b[3][4];
#pragma unroll
            for (int mi = 0; mi < 4; mi++) {
                int row = warp_m * 64 + mi * 16 + lr;
                ldsm4(a[mi], stage + row * 128 + cs * 16);
            }
#pragma unroll
            for (int q = 0; q < 3; q++) {
                int row = AROWS + warp_n * 48 + q * 16 + lr;
                ldsm4(b[q], stage + row * 128 + cs * 16);
            }
#pragma unroll
            for (int mi = 0; mi < 4; mi++)
#pragma unroll
                for (int q = 0; q < 3; q++) {
                    mma_f16(acc[mi][2 * q],     a[mi], b[q][0], b[q][2]);
                    mma_f16(acc[mi][2 * q + 1], a[mi], b[q][1], b[q][3]);
                }
        }
    }
    asm volatile("cp.async.wait_group 0;");
    __syncthreads();

#pragma unroll
    for (int mi = 0; mi < 4; mi++)
#pragma unroll
        for (int ni = 0; ni < 6; ni++) {
            int row = bm + warp_m * 64 + mi * 16 + (l >> 2);
            int col = bn + warp_n * 48 + ni * 8 + (l & 3) * 2;
            float b0 = bias[col], b1 = bias[col + 1];
            *(float2*)&out[(size_t)row * N_DIM + col] =
                make_float2(acc[mi][ni][0] + b0, acc[mi][ni][1] + b1);
            *(float2*)&out[(size_t)(row + 8) * N_DIM + col] =
                make_float2(acc[mi][ni][2] + b0, acc[mi][ni][3] + b1);
        }
}

extern "C" void kernel_launch(void* const* d_in, const int* in_sizes, int n_in,
                              void* d_out, int out_size)
{
    const float* x      = (const float*)d_in[0];
    const float* W_proj = (const float*)d_in[1];
    const float* b_proj = (const float*)d_in[2];
    const float* theta  = (const float*)d_in[3];
    const float* W_comb = (const float*)d_in[4];
    const float* b_comb = (const float*)d_in[5];
    float* out = (float*)d_out;

    cudaFuncSetAttribute(qgemm1, cudaFuncAttributeMaxDynamicSharedMemorySize, S1_SMEM);
    cudaFuncSetAttribute(gemm2,  cudaFuncAttributeMaxDynamicSharedMemorySize, S2_SMEM);

    __half *Bp, *Bc, *E;
    cudaGetSymbolAddress((void**)&Bp, g_Bp);
    cudaGetSymbolAddress((void**)&Bc, g_Bc);
    cudaGetSymbolAddress((void**)&E,  g_E);

    const int total16 = 2 * (N_DIM * KD / 16);   // 73728
    conv_kernel<<<(total16 + 255) / 256, 256>>>(W_proj, W_comb);

    dim3 grid(N_DIM / BN, M_DIM / BM);  // (4, 32) = 128 CTAs, single wave
    qgemm1<<<grid, THREADS, S1_SMEM>>>(x, Bp, b_proj, theta, E);
    gemm2<<<grid, THREADS, S2_SMEM>>>(E, Bc, b_comb, out);
}